// round 1
// baseline (speedup 1.0000x reference)
#include <cuda_runtime.h>
#include <cstdint>
#include <cstring>

#define Nn 32768
#define Dd 512
#define Cc 64
#define Kk 16
#define Mm 512
#define Jj 256   // C*DEPTH

// ---------------- scratch (no allocations allowed) ----------------
__device__ float d_Lt[Cc * Kk * Mm];          // [c][k][m]  2 MB
__device__ unsigned char d_idx[Nn * Cc];      // [n][c]     2 MB

// ---------------- K0: transpose L (M,C,K) -> Lt (C*K, M) ----------------
// View L as X[512][1024] (m-major, ck contiguous); produce Y[1024][512].
__global__ void k_transpose(const float* __restrict__ L) {
    __shared__ float tile[32][33];
    int bx = blockIdx.x * 32;   // ck
    int by = blockIdx.y * 32;   // m
    for (int i = threadIdx.y; i < 32; i += 8)
        tile[i][threadIdx.x] = L[(size_t)(by + i) * (Cc * Kk) + bx + threadIdx.x];
    __syncthreads();
    for (int i = threadIdx.y; i < 32; i += 8)
        d_Lt[(size_t)(bx + i) * Mm + by + threadIdx.x] = tile[threadIdx.x][i];
}

// ---------------- K1: fused GEMM (P = I @ A) + tree traversal -> idx ----------------
__device__ __forceinline__ unsigned trav(const float* __restrict__ Tc,
                                         float f0, float f1, float f2, float f3) {
    float f[4] = {f0, f1, f2, f3};
    unsigned node = 0, k = 0;
#pragma unroll
    for (int l = 0; l < 4; l++) {
        unsigned bit = (f[l] > __ldg(&Tc[node])) ? 1u : 0u;
        k = (k << 1) | bit;
        node = 2 * node + 1 + bit;
    }
    return k;
}

#define BM 128
#define BN 128
#define BK 32

__global__ __launch_bounds__(256) void k_gemm_tree(
    const float* __restrict__ I, const float* __restrict__ A,
    const float* __restrict__ T)
{
    __shared__ float Is[BK][132];   // k-major, padded (132*4=528B, 16B aligned rows)
    __shared__ float As[BK][BN];

    int tid = threadIdx.x;
    int tx = tid & 15;
    int ty = tid >> 4;
    int rowBase = blockIdx.y * BM;
    int colBase = blockIdx.x * BN;

    unsigned long long acc[8][4];   // 8 rows x 4 col-pairs, packed f32x2
#pragma unroll
    for (int i = 0; i < 8; i++)
#pragma unroll
        for (int j = 0; j < 4; j++) acc[i][j] = 0ull;

    int r  = tid >> 3;   // 0..31 (I-tile row group)
    int kv = tid & 7;    // float4 index along k
    int kk = tid >> 5;   // 0..7  (A-tile k row group)
    int jv = tid & 31;   // float4 index along j

    for (int kt = 0; kt < Dd; kt += BK) {
        // load I tile (128 rows x 32 k), store transposed into Is[k][row]
#pragma unroll
        for (int q = 0; q < 4; q++) {
            int lr = r + q * 32;
            float4 v = *(const float4*)&I[(size_t)(rowBase + lr) * Dd + kt + kv * 4];
            Is[kv * 4 + 0][lr] = v.x;
            Is[kv * 4 + 1][lr] = v.y;
            Is[kv * 4 + 2][lr] = v.z;
            Is[kv * 4 + 3][lr] = v.w;
        }
        // load A tile (32 k x 128 j)
#pragma unroll
        for (int q = 0; q < 4; q++)
            *(float4*)&As[kk + q * 8][jv * 4] =
                *(const float4*)&A[(size_t)(kt + kk + q * 8) * Jj + colBase + jv * 4];
        __syncthreads();

#pragma unroll
        for (int kx = 0; kx < BK; kx++) {
            float4 a0 = *(const float4*)&Is[kx][ty * 8];
            float4 a1 = *(const float4*)&Is[kx][ty * 8 + 4];
            ulonglong2 b0 = *(const ulonglong2*)&As[kx][tx * 8];
            ulonglong2 b1 = *(const ulonglong2*)&As[kx][tx * 8 + 4];
            unsigned long long bp[4] = {b0.x, b0.y, b1.x, b1.y};
            float av[8] = {a0.x, a0.y, a0.z, a0.w, a1.x, a1.y, a1.z, a1.w};
#pragma unroll
            for (int i = 0; i < 8; i++) {
                unsigned long long ap;
                asm("mov.b64 %0, {%1, %2};" : "=l"(ap) : "f"(av[i]), "f"(av[i]));
#pragma unroll
                for (int j = 0; j < 4; j++)
                    asm("fma.rn.f32x2 %0, %1, %2, %0;"
                        : "+l"(acc[i][j]) : "l"(ap), "l"(bp[j]));
            }
        }
        __syncthreads();
    }

    // epilogue: each thread owns 8 consecutive j = 2 complete codebooks
    int cg = (colBase + tx * 8) >> 2;   // global codebook index (even)
#pragma unroll
    for (int i = 0; i < 8; i++) {
        int n = rowBase + ty * 8 + i;
        float f[8];
#pragma unroll
        for (int j = 0; j < 4; j++)
            asm("mov.b64 {%0, %1}, %2;" : "=f"(f[2 * j]), "=f"(f[2 * j + 1]) : "l"(acc[i][j]));
        unsigned k1 = trav(&T[cg * 15],       f[0], f[1], f[2], f[3]);
        unsigned k2 = trav(&T[(cg + 1) * 15], f[4], f[5], f[6], f[7]);
        uchar2 st;
        st.x = (unsigned char)k1;
        st.y = (unsigned char)k2;
        *(uchar2*)&d_idx[(size_t)n * Cc + cg] = st;
    }
}

// ---------------- K3: LUT accumulate out[n,m] = sum_c Lt[c, idx[n,c], m] ----------------
#define K3_ROWS 256
#define K3_MT   32
#define K3_SMEM (Cc * Kk * K3_MT * 4 + K3_ROWS * Cc)   // 128KB Ls + 16KB idx = 147456

__global__ __launch_bounds__(256) void k_lut(float* __restrict__ out) {
    extern __shared__ char smraw[];
    float* Ls = (float*)smraw;                               // [c][k][32m]
    unsigned char* idxs = (unsigned char*)(smraw + Cc * Kk * K3_MT * 4); // [256r][64c]

    int tid = threadIdx.x;
    int rowBase = blockIdx.y * K3_ROWS;
    int mBase   = blockIdx.x * K3_MT;

    // load Ls slice: 64*16 rows of 32 floats (8 float4 each)
    for (int i = tid; i < Cc * Kk * (K3_MT / 4); i += 256) {
        int ck = i >> 3;
        int mv = i & 7;
        *(float4*)&Ls[ck * K3_MT + mv * 4] =
            *(const float4*)&d_Lt[(size_t)ck * Mm + mBase + mv * 4];
    }
    // load idx tile: 256 rows x 64 bytes
    for (int i = tid; i < K3_ROWS * Cc / 8; i += 256)
        *(unsigned long long*)&idxs[i * 8] =
            *(const unsigned long long*)&d_idx[(size_t)rowBase * Cc + i * 8];
    __syncthreads();

    int mp = tid & 15;    // m-pair lane (2 floats)
    int rg = tid >> 4;    // row group 0..15 (16 rows each)

    unsigned long long acc[16];
#pragma unroll
    for (int i = 0; i < 16; i++) acc[i] = 0ull;

    int mOff = mp * 2;
#pragma unroll 1
    for (int c4 = 0; c4 < 16; c4++) {
#pragma unroll
        for (int rr = 0; rr < 16; rr++) {
            int row = rg * 16 + rr;
            unsigned k4 = *(const unsigned*)&idxs[row * Cc + c4 * 4];
#pragma unroll
            for (int j = 0; j < 4; j++) {
                unsigned k = (k4 >> (8 * j)) & 15u;
                int c = c4 * 4 + j;
                unsigned long long lv =
                    *(const unsigned long long*)&Ls[(c * Kk + k) * K3_MT + mOff];
                asm("add.rn.f32x2 %0, %0, %1;" : "+l"(acc[rr]) : "l"(lv));
            }
        }
    }

#pragma unroll
    for (int rr = 0; rr < 16; rr++) {
        int row = rowBase + rg * 16 + rr;
        *(unsigned long long*)&out[(size_t)row * Mm + mBase + mOff] = acc[rr];
    }
}

// ---------------- launch ----------------
extern "C" void kernel_launch(void* const* d_in, const int* in_sizes, int n_in,
                              void* d_out, int out_size) {
    const float *I = nullptr, *T = nullptr, *L = nullptr, *A = nullptr;
    for (int i = 0; i < n_in; i++) {
        switch (in_sizes[i]) {
            case Nn * Dd:      I = (const float*)d_in[i]; break;  // 16777216
            case 960:          T = (const float*)d_in[i]; break;  // C*15
            case Mm * Cc * Kk: L = (const float*)d_in[i]; break;  // 524288
            case Dd * Jj:      A = (const float*)d_in[i]; break;  // 131072
            default: break;  // S (245760), B (983040) unused — structure hardcoded
        }
    }
    float* out = (float*)d_out;

    cudaFuncSetAttribute(k_lut, cudaFuncAttributeMaxDynamicSharedMemorySize, K3_SMEM);

    dim3 g0(32, 16), b0(32, 8);
    k_transpose<<<g0, b0>>>(L);

    dim3 g1(Jj / BN, Nn / BM);      // (2, 256)
    k_gemm_tree<<<g1, 256>>>(I, A, T);

    dim3 g3(Mm / K3_MT, Nn / K3_ROWS);  // (16, 128)
    k_lut<<<g3, 256, K3_SMEM>>>(out);
}